// round 10
// baseline (speedup 1.0000x reference)
#include <cuda_runtime.h>

#define BATCH 512
#define INF   512
#define OUTF  100
#define KD    5
#define OKC   500            // OUTF * KD
#define PLANE (OKC * BATCH)  // 256000
#define NZ    8              // split-K factor (K-slice = 64)
#define LOG2E 1.4426950408889634f

typedef unsigned long long u64;

// M in [c][b] layout (c = o*KD+k), pre-scaled by log2e. Accumulated via REDG.
__device__ __align__(16) float g_M[PLANE];

// ---- packed f32x2 helpers (asm only) ----
__device__ __forceinline__ u64 f2add(u64 a, u64 b) {
    u64 r; asm("add.rn.f32x2 %0,%1,%2;" : "=l"(r) : "l"(a), "l"(b)); return r;
}
__device__ __forceinline__ u64 f2fma(u64 a, u64 b, u64 c) {
    u64 r; asm("fma.rn.f32x2 %0,%1,%2,%3;" : "=l"(r) : "l"(a), "l"(b), "l"(c)); return r;
}
__device__ __forceinline__ u64 pk(float lo, float hi) {
    u64 r; asm("mov.b64 %0,{%1,%2};" : "=l"(r) : "f"(lo), "f"(hi)); return r;
}
__device__ __forceinline__ void upk(u64 a, float& lo, float& hi) {
    asm("mov.b64 {%0,%1},%2;" : "=f"(lo), "=f"(hi) : "l"(a));
}
__device__ __forceinline__ u64 dup2(float v) { return pk(v, v); }
__device__ __forceinline__ float ex2_approx(float x) {
    float y; asm("ex2.approx.ftz.f32 %0, %1;" : "=f"(y) : "f"(x)); return y;
}
#define NEGABS_MASK 0x8000000080000000ULL   // OR -> -(|x|) on both halves

// ---------------------------------------------------------------------------
// Kernel 0: zero g_M (atomically accumulated by the GEMM).
// ---------------------------------------------------------------------------
__global__ void __launch_bounds__(256)
zero_kernel() {
    ((float4*)g_M)[blockIdx.x * 256 + threadIdx.x] = make_float4(0.f, 0.f, 0.f, 0.f);
}

// ---------------------------------------------------------------------------
// Kernel 1: split-K GEMM, single BK=64 slab, ZERO mainloop barriers.
// Block tile 64m x 64n, 256 threads, thread tile 4m(2 u64) x 4n.
// Prologue: 8 LDG.128 + transpose-A/copy-B to smem + ONE __syncthreads.
// Mainloop: 64 unrolled kk, per kk: 2 LDS.128 + 4 dup MOV + 8 FFMA2.
// Epilogue: atomicAdd (REDG, no return) into g_M -- replaces reduce kernel.
// grid = (8 n, 8 m, 8 z) = 512 blocks.
// ---------------------------------------------------------------------------
__global__ void __launch_bounds__(256, 3)
gemm_kernel(const float* __restrict__ X, const float* __restrict__ W) {
    __shared__ __align__(16) float As[64][64];   // [kk][m]  16 KB
    __shared__ __align__(16) float Bs[64][64];   // [kk][n]  16 KB

    const int tid = threadIdx.x;
    const int tx  = tid & 15;          // n quad (4 n each)
    const int ty  = tid >> 4;          // m quad (4 m each)
    const int n0  = blockIdx.x * 64;
    const int m0  = blockIdx.y * 64;
    const int k0  = blockIdx.z * 64;

    // ---- prologue ----
    // A: thread owns X row ar, 16 consecutive k at kq. Stores transposed:
    // each STS.32 writes 32 consecutive floats of one kk-row -> conflict-free.
    const int ar = tid & 63;
    const int kq = (tid >> 6) * 16;
    const float* xp = X + (m0 + ar) * INF + k0 + kq;
    float4 a4[4];
    #pragma unroll
    for (int q = 0; q < 4; q++) a4[q] = *(const float4*)(xp + q * 4);
    #pragma unroll
    for (int q = 0; q < 4; q++) {
        As[kq + q * 4 + 0][ar] = a4[q].x;
        As[kq + q * 4 + 1][ar] = a4[q].y;
        As[kq + q * 4 + 2][ar] = a4[q].z;
        As[kq + q * 4 + 3][ar] = a4[q].w;
    }
    // B: thread covers 4 rows (kr, kr+16, kr+32, kr+48), one col quad.
    const int kr  = tid >> 4;
    const int bcl = (tid & 15) * 4;
    const bool bok = (n0 + bcl) < OKC;     // OKC % 4 == 0 -> per-quad validity
    const float* wp = W + (k0 + kr) * OKC + n0 + bcl;
    const float4 fz = make_float4(0.f, 0.f, 0.f, 0.f);
    float4 b4[4];
    #pragma unroll
    for (int p = 0; p < 4; p++)
        b4[p] = bok ? *(const float4*)(wp + p * 16 * OKC) : fz;
    #pragma unroll
    for (int p = 0; p < 4; p++)
        *(float4*)&Bs[kr + p * 16][bcl] = b4[p];
    __syncthreads();                       // the ONLY barrier

    // ---- mainloop: 64 kk, no syncs ----
    u64 acc[2][4];                         // [m-pair][n]
    #pragma unroll
    for (int p = 0; p < 2; p++)
        #pragma unroll
        for (int j = 0; j < 4; j++) acc[p][j] = 0ULL;

    #pragma unroll
    for (int kk = 0; kk < 64; kk++) {
        ulonglong2 A = *(const ulonglong2*)&As[kk][ty * 4];
        float4 bq = *(const float4*)&Bs[kk][tx * 4];
        u64 b0 = pk(bq.x, bq.x);
        u64 b1 = pk(bq.y, bq.y);
        u64 b2 = pk(bq.z, bq.z);
        u64 b3 = pk(bq.w, bq.w);
        acc[0][0] = f2fma(A.x, b0, acc[0][0]);
        acc[1][0] = f2fma(A.y, b0, acc[1][0]);
        acc[0][1] = f2fma(A.x, b1, acc[0][1]);
        acc[1][1] = f2fma(A.y, b1, acc[1][1]);
        acc[0][2] = f2fma(A.x, b2, acc[0][2]);
        acc[1][2] = f2fma(A.y, b2, acc[1][2]);
        acc[0][3] = f2fma(A.x, b3, acc[0][3]);
        acc[1][3] = f2fma(A.y, b3, acc[1][3]);
    }

    // ---- epilogue: accumulate into g_M via REDG (no reduce kernel) ----
    #pragma unroll
    for (int j = 0; j < 4; j++) {
        int c = n0 + tx * 4 + j;
        if (c < OKC) {
            float v0, v1, v2, v3;
            upk(acc[0][j], v0, v1);
            upk(acc[1][j], v2, v3);
            float* dst = &g_M[c * BATCH + m0 + ty * 4];
            atomicAdd(dst + 0, v0 * LOG2E);
            atomicAdd(dst + 1, v1 * LOG2E);
            atomicAdd(dst + 2, v2 * LOG2E);
            atomicAdd(dst + 3, v3 * LOG2E);
        }
    }
}

// ---------------------------------------------------------------------------
// Kernel 2: pairwise, uniform-i / register-j (R5/R8 design).
// grid = (100, 8) = 800 blocks x 256 thr; thread owns j = tid, tid+256.
// ---------------------------------------------------------------------------
__global__ void __launch_bounds__(256)
pairwise_kernel(float* __restrict__ out) {
    const int o  = blockIdx.x;
    const int z  = blockIdx.y;
    const int i0 = z * 64;
    const int tid = threadIdx.x;
    const int j1 = tid, j2 = tid + 256;

    __shared__ __align__(16) float sP[32][12];   // pair q: (M[2q,k],M[2q+1,k]), pad

    const float* base = g_M + o * KD * BATCH;

    #pragma unroll
    for (int idx = tid; idx < 64 * KD; idx += 256) {
        int k = idx >> 6, b = idx & 63;
        sP[b >> 1][2 * k + (b & 1)] = base[k * BATCH + i0 + b];
    }

    u64 nm1[KD], nm2[KD];
    #pragma unroll
    for (int k = 0; k < KD; k++) {
        nm1[k] = dup2(-base[k * BATCH + j1]);
        nm2[k] = dup2(-base[k * BATCH + j2]);
    }
    __syncthreads();

    float acc1a = 0.f, acc1b = 0.f, acc2a = 0.f, acc2b = 0.f;

    #pragma unroll 8
    for (int s = 0; s < 32; s++) {
        const float* row = &sP[s][0];
        ulonglong2 q01 = *(const ulonglong2*)(row);
        ulonglong2 q23 = *(const ulonglong2*)(row + 4);
        u64 p4 = *(const u64*)(row + 8);
        {
            u64 d0 = f2add(q01.x, nm1[0]) | NEGABS_MASK;
            u64 d1 = f2add(q01.y, nm1[1]) | NEGABS_MASK;
            u64 d2 = f2add(q23.x, nm1[2]) | NEGABS_MASK;
            u64 d3 = f2add(q23.y, nm1[3]) | NEGABS_MASK;
            u64 d4 = f2add(p4,    nm1[4]) | NEGABS_MASK;
            u64 t = f2add(f2add(f2add(d0, d1), f2add(d2, d3)), d4);
            float tf0, tf1; upk(t, tf0, tf1);
            acc1a += ex2_approx(tf0);
            acc1b += ex2_approx(tf1);
        }
        {
            u64 d0 = f2add(q01.x, nm2[0]) | NEGABS_MASK;
            u64 d1 = f2add(q01.y, nm2[1]) | NEGABS_MASK;
            u64 d2 = f2add(q23.x, nm2[2]) | NEGABS_MASK;
            u64 d3 = f2add(q23.y, nm2[3]) | NEGABS_MASK;
            u64 d4 = f2add(p4,    nm2[4]) | NEGABS_MASK;
            u64 t = f2add(f2add(f2add(d0, d1), f2add(d2, d3)), d4);
            float tf0, tf1; upk(t, tf0, tf1);
            acc2a += ex2_approx(tf0);
            acc2b += ex2_approx(tf1);
        }
    }

    float r1 = acc1a + acc1b;
    float r2 = acc2a + acc2b;
    if ((j1 >> 6) == z) r1 -= 1.0f;   // self term exp2(-0) = 1
    if ((j2 >> 6) == z) r2 -= 1.0f;
    atomicAdd(&out[j1 * OUTF + o], r1);
    atomicAdd(&out[j2 * OUTF + o], r2);
}

// ---------------------------------------------------------------------------
extern "C" void kernel_launch(void* const* d_in, const int* in_sizes, int n_in,
                              void* d_out, int out_size) {
    const float* x = (const float*)d_in[0];   // [512, 512]
    const float* T = (const float*)d_in[1];   // [512, 100, 5] == [512, 500]
    float* out = (float*)d_out;               // [512, 100]

    cudaMemsetAsync(out, 0, BATCH * OUTF * sizeof(float));

    zero_kernel<<<PLANE / 4 / 256, 256>>>();  // 250 blocks, zeros g_M

    dim3 ggrid(8, 8, NZ);                     // 512 blocks
    gemm_kernel<<<ggrid, 256>>>(x, T);

    dim3 pgrid(OUTF, 8);                      // 800 blocks
    pairwise_kernel<<<pgrid, 256>>>(out);
}

// round 11
// speedup vs baseline: 1.0606x; 1.0606x over previous
#include <cuda_runtime.h>

#define BATCH 512
#define INF   512
#define OUTF  100
#define KD    5
#define OKC   500            // OUTF * KD
#define PLANE (OKC * BATCH)  // 256000
#define NZ    8              // split-K factor (K-slice = 64)
#define LOG2E 1.4426950408889634f

typedef unsigned long long u64;

// Split-K partials [z][c][b] (c = o*KD+k), and the reduced M, both *log2e.
__device__ __align__(16) float g_Mp[NZ][PLANE];
__device__ __align__(16) float g_M[PLANE];

// ---- packed f32x2 helpers (asm only) ----
__device__ __forceinline__ u64 f2add(u64 a, u64 b) {
    u64 r; asm("add.rn.f32x2 %0,%1,%2;" : "=l"(r) : "l"(a), "l"(b)); return r;
}
__device__ __forceinline__ u64 f2fma(u64 a, u64 b, u64 c) {
    u64 r; asm("fma.rn.f32x2 %0,%1,%2,%3;" : "=l"(r) : "l"(a), "l"(b), "l"(c)); return r;
}
__device__ __forceinline__ u64 pk(float lo, float hi) {
    u64 r; asm("mov.b64 %0,{%1,%2};" : "=l"(r) : "f"(lo), "f"(hi)); return r;
}
__device__ __forceinline__ void upk(u64 a, float& lo, float& hi) {
    asm("mov.b64 {%0,%1},%2;" : "=f"(lo), "=f"(hi) : "l"(a));
}
__device__ __forceinline__ u64 dup2(float v) { return pk(v, v); }
__device__ __forceinline__ float ex2_approx(float x) {
    float y; asm("ex2.approx.ftz.f32 %0, %1;" : "=f"(y) : "f"(x)); return y;
}
#define NEGABS_MASK 0x8000000080000000ULL   // OR -> -(|x|) on both halves

// ---------------------------------------------------------------------------
// Kernel 1: split-K GEMM (R8 shape) at 4 CTAs/SM -> single full wave.
// Block tile 64m x 64n, BK=16, K-slice 64 (4 k-tiles, double buffered),
// 256 threads, thread tile 4m(2 u64) x 4n. A transposed in smem; B quad via
// one LDS.128, duplicated in registers. 8 FFMA2 per kk per thread.
// grid = (8 n, 8 m, 8 z) = 512 blocks < 592 = 4 CTAs/SM x 148 -> no tail wave.
// ---------------------------------------------------------------------------
__global__ void __launch_bounds__(256, 4)
gemm_kernel(const float* __restrict__ X, const float* __restrict__ W) {
    __shared__ __align__(16) float As[2][16][64];    // [buf][kk][m]  8 KB
    __shared__ __align__(16) float Bs[2][16][64];    // [buf][kk][n]  8 KB

    const int tid = threadIdx.x;
    const int tx  = tid & 15;          // n quad (4 n each)
    const int ty  = tid >> 4;          // m quad (4 m each)
    const int n0  = blockIdx.x * 64;
    const int m0  = blockIdx.y * 64;
    const int k0  = blockIdx.z * 64;

    // A loader: row ar (0..63), k quad ak (0/4/8/12); stores transposed.
    const int ar = tid >> 2;
    const int ak = (tid & 3) * 4;
    const float* xp = X + (m0 + ar) * INF + k0 + ak;

    // B loader: kk-row bkr (0..15), col quad bcl; OKC % 4 == 0.
    const int bkr = tid >> 4;
    const int bcl = (tid & 15) * 4;
    const int bc  = n0 + bcl;
    const bool bok = bc < OKC;
    const float* wp = W + (k0 + bkr) * OKC + bc;
    const float4 fz = make_float4(0.f, 0.f, 0.f, 0.f);

    // prologue: k-tile 0 -> buf 0
    float4 av = *(const float4*)xp;
    float4 bv = bok ? *(const float4*)wp : fz;
    As[0][ak + 0][ar] = av.x;
    As[0][ak + 1][ar] = av.y;
    As[0][ak + 2][ar] = av.z;
    As[0][ak + 3][ar] = av.w;
    *(float4*)&Bs[0][bkr][bcl] = bv;
    __syncthreads();

    u64 acc[2][4];                     // [m-pair][n]
    #pragma unroll
    for (int p = 0; p < 2; p++)
        #pragma unroll
        for (int j = 0; j < 4; j++) acc[p][j] = 0ULL;

    #pragma unroll
    for (int kt = 0; kt < 4; kt++) {
        const int cur = kt & 1;
        if (kt < 3) {                  // prefetch next k-tile into registers
            av = *(const float4*)(xp + (kt + 1) * 16);
            bv = bok ? *(const float4*)(wp + (kt + 1) * 16 * OKC) : fz;
        }
        #pragma unroll
        for (int kk = 0; kk < 16; kk++) {
            ulonglong2 A = *(const ulonglong2*)&As[cur][kk][ty * 4];
            float4 bq = *(const float4*)&Bs[cur][kk][tx * 4];
            u64 b0 = pk(bq.x, bq.x);
            u64 b1 = pk(bq.y, bq.y);
            u64 b2 = pk(bq.z, bq.z);
            u64 b3 = pk(bq.w, bq.w);
            acc[0][0] = f2fma(A.x, b0, acc[0][0]);
            acc[1][0] = f2fma(A.y, b0, acc[1][0]);
            acc[0][1] = f2fma(A.x, b1, acc[0][1]);
            acc[1][1] = f2fma(A.y, b1, acc[1][1]);
            acc[0][2] = f2fma(A.x, b2, acc[0][2]);
            acc[1][2] = f2fma(A.y, b2, acc[1][2]);
            acc[0][3] = f2fma(A.x, b3, acc[0][3]);
            acc[1][3] = f2fma(A.y, b3, acc[1][3]);
        }
        if (kt < 3) {                  // stage prefetched tile -> other buffer
            const int nxt = cur ^ 1;
            As[nxt][ak + 0][ar] = av.x;
            As[nxt][ak + 1][ar] = av.y;
            As[nxt][ak + 2][ar] = av.z;
            As[nxt][ak + 3][ar] = av.w;
            *(float4*)&Bs[nxt][bkr][bcl] = bv;
            __syncthreads();
        }
    }

    // epilogue: store [c][b] scaled by log2e; 4 m values contiguous.
    float* plane = g_Mp[blockIdx.z];
    #pragma unroll
    for (int j = 0; j < 4; j++) {
        int c = n0 + tx * 4 + j;
        if (c < OKC) {
            float v0, v1, v2, v3;
            upk(acc[0][j], v0, v1);
            upk(acc[1][j], v2, v3);
            float4 o = make_float4(v0 * LOG2E, v1 * LOG2E, v2 * LOG2E, v3 * LOG2E);
            *(float4*)&plane[c * BATCH + m0 + ty * 4] = o;
        }
    }
}

// ---------------------------------------------------------------------------
// Kernel 1b: collapse the NZ split-K planes once (L2-resident traffic).
// ---------------------------------------------------------------------------
__global__ void __launch_bounds__(256)
reduce_kernel() {
    const int i = blockIdx.x * 256 + threadIdx.x;      // float4 index
    float4 s = ((const float4*)g_Mp[0])[i];
    #pragma unroll
    for (int z = 1; z < NZ; z++) {
        float4 t = ((const float4*)g_Mp[z])[i];
        s.x += t.x; s.y += t.y; s.z += t.z; s.w += t.w;
    }
    ((float4*)g_M)[i] = s;
}

// ---------------------------------------------------------------------------
// Kernel 2: pairwise, uniform-i / register-j (R5/R8 design).
// grid = (100, 8) = 800 blocks x 256 thr; thread owns j = tid, tid+256.
// ---------------------------------------------------------------------------
__global__ void __launch_bounds__(256)
pairwise_kernel(float* __restrict__ out) {
    const int o  = blockIdx.x;
    const int z  = blockIdx.y;
    const int i0 = z * 64;
    const int tid = threadIdx.x;
    const int j1 = tid, j2 = tid + 256;

    __shared__ __align__(16) float sP[32][12];   // pair q: (M[2q,k],M[2q+1,k]), pad

    const float* base = g_M + o * KD * BATCH;

    #pragma unroll
    for (int idx = tid; idx < 64 * KD; idx += 256) {
        int k = idx >> 6, b = idx & 63;
        sP[b >> 1][2 * k + (b & 1)] = base[k * BATCH + i0 + b];
    }

    u64 nm1[KD], nm2[KD];
    #pragma unroll
    for (int k = 0; k < KD; k++) {
        nm1[k] = dup2(-base[k * BATCH + j1]);
        nm2[k] = dup2(-base[k * BATCH + j2]);
    }
    __syncthreads();

    float acc1a = 0.f, acc1b = 0.f, acc2a = 0.f, acc2b = 0.f;

    #pragma unroll 8
    for (int s = 0; s < 32; s++) {
        const float* row = &sP[s][0];
        ulonglong2 q01 = *(const ulonglong2*)(row);
        ulonglong2 q23 = *(const ulonglong2*)(row + 4);
        u64 p4 = *(const u64*)(row + 8);
        {
            u64 d0 = f2add(q01.x, nm1[0]) | NEGABS_MASK;
            u64 d1 = f2add(q01.y, nm1[1]) | NEGABS_MASK;
            u64 d2 = f2add(q23.x, nm1[2]) | NEGABS_MASK;
            u64 d3 = f2add(q23.y, nm1[3]) | NEGABS_MASK;
            u64 d4 = f2add(p4,    nm1[4]) | NEGABS_MASK;
            u64 t = f2add(f2add(f2add(d0, d1), f2add(d2, d3)), d4);
            float tf0, tf1; upk(t, tf0, tf1);
            acc1a += ex2_approx(tf0);
            acc1b += ex2_approx(tf1);
        }
        {
            u64 d0 = f2add(q01.x, nm2[0]) | NEGABS_MASK;
            u64 d1 = f2add(q01.y, nm2[1]) | NEGABS_MASK;
            u64 d2 = f2add(q23.x, nm2[2]) | NEGABS_MASK;
            u64 d3 = f2add(q23.y, nm2[3]) | NEGABS_MASK;
            u64 d4 = f2add(p4,    nm2[4]) | NEGABS_MASK;
            u64 t = f2add(f2add(f2add(d0, d1), f2add(d2, d3)), d4);
            float tf0, tf1; upk(t, tf0, tf1);
            acc2a += ex2_approx(tf0);
            acc2b += ex2_approx(tf1);
        }
    }

    float r1 = acc1a + acc1b;
    float r2 = acc2a + acc2b;
    if ((j1 >> 6) == z) r1 -= 1.0f;   // self term exp2(-0) = 1
    if ((j2 >> 6) == z) r2 -= 1.0f;
    atomicAdd(&out[j1 * OUTF + o], r1);
    atomicAdd(&out[j2 * OUTF + o], r2);
}

// ---------------------------------------------------------------------------
extern "C" void kernel_launch(void* const* d_in, const int* in_sizes, int n_in,
                              void* d_out, int out_size) {
    const float* x = (const float*)d_in[0];   // [512, 512]
    const float* T = (const float*)d_in[1];   // [512, 100, 5] == [512, 500]
    float* out = (float*)d_out;               // [512, 100]

    cudaMemsetAsync(out, 0, BATCH * OUTF * sizeof(float));

    dim3 ggrid(8, 8, NZ);                     // 512 blocks, one 4-CTA/SM wave
    gemm_kernel<<<ggrid, 256>>>(x, T);

    reduce_kernel<<<PLANE / 4 / 256, 256>>>();  // 250 blocks

    dim3 pgrid(OUTF, 8);                      // 800 blocks
    pairwise_kernel<<<pgrid, 256>>>(out);
}